// round 6
// baseline (speedup 1.0000x reference)
#include <cuda_runtime.h>

// CapLayer fused capsule routing. 512 threads/CTA, 2 CTAs/SM.
// All W/bias streams fully coalesced; Phase E uses warp-per-tile + shuffle reduce.
// x:    d_in[0]  float [512][256][6][6]   (channel = g*8+k, g<32, k<8)
// W:    d_in[2]  float [5120][8] ; flat = g*1280 + j*128 + d*8 + k
// bias: d_in[3]  float [5120]    ; flat = g*160  + j*16  + d
// out:  float [512][10][16]

#define LOG2E 1.4426950408889634f

struct Smem {
    float x[32 * 8 * 36];     // 9216  [g][k][hw]
    float cbuf[16 * 10 * 36]; // 5760  per-warp c scratch [w][j][hw]
    float vW[10 * 32 * 8];    // 2560  [j][g][k]  (accum, pre-scaled by log2e)
    float vb[10 * 32];        // 320   [j][g]
    float cx[10 * 32 * 8];    // 2560  [j][g][k]
    float csum[10 * 32];      // 320   [j][g]
    float sW[160];
    float sB[160];
    float v[160];
    float xsum[256];          // [g][k]
};                            // 21472 floats = 85888 B  (2 CTAs/SM)

__device__ __forceinline__ float ex2_approx(float x) {
    float y; asm("ex2.approx.ftz.f32 %0, %1;" : "=f"(y) : "f"(x)); return y;
}
__device__ __forceinline__ float rcp_approx(float x) {
    float y; asm("rcp.approx.ftz.f32 %0, %1;" : "=f"(y) : "f"(x)); return y;
}
__device__ __forceinline__ float dot4(float4 a, float4 b) {
    return a.x * b.x + a.y * b.y + a.z * b.z + a.w * b.w;
}
__device__ __forceinline__ float sum4(float4 a) {
    return a.x + a.y + a.z + a.w;
}

__global__ __launch_bounds__(512, 2)
void caps_kernel(const float* __restrict__ x_g,
                 const float* __restrict__ W,
                 const float* __restrict__ bias,
                 float* __restrict__ out) {
    extern __shared__ float smem_raw[];
    Smem* S = reinterpret_cast<Smem*>(smem_raw);

    const int b    = blockIdx.x;
    const int tid  = threadIdx.x;
    const int w    = tid >> 5;
    const int lane = tid & 31;

    // ---- load x ([g][k][hw] contiguous) ----
    {
        const float4* src = reinterpret_cast<const float4*>(x_g + (size_t)b * 9216);
        float4* dst = reinterpret_cast<float4*>(S->x);
        #pragma unroll
        for (int i = 0; i < 5; i++) {
            int idx = tid + i * 512;
            if (idx < 2304) dst[idx] = src[idx];
        }
    }
    __syncthreads();

    // ---- xsum[g][k] = sum_hw x ----
    if (tid < 256) {
        const float4* p = reinterpret_cast<const float4*>(S->x + tid * 36);
        float4 a4 = p[0];
        #pragma unroll
        for (int t = 1; t < 9; t++) {
            float4 q = p[t];
            a4.x += q.x; a4.y += q.y; a4.z += q.z; a4.w += q.w;
        }
        S->xsum[tid] = sum4(a4);
    }
    __syncthreads();

    // iter 1: c uniform 0.1 -> cx = 0.1*xsum (all j), csum = 3.6
    for (int i = tid; i < 2560; i += 512) S->cx[i] = 0.1f * S->xsum[i & 255];
    if (tid < 320) S->csum[tid] = 3.6f;
    __syncthreads();

    for (int it = 0; it < 3; ++it) {
        if (it > 0) {
            // ===== Phase A+B per warp; warp handles groups w and w+16 =====
            #pragma unroll
            for (int gi = 0; gi < 2; gi++) {
                const int g = w + gi * 16;
                // --- Phase A: logits -> softmax over j -> c (per-warp buffer) ---
                {
                    const float* xr = S->x + g * 8 * 36;
                    float xv[8], xv2[8];
                    #pragma unroll
                    for (int k = 0; k < 8; k++) {
                        xv[k]  = xr[k * 36 + lane];
                        xv2[k] = xr[k * 36 + 32 + (lane & 3)];
                    }
                    float bb[10], bb2[10];
                    #pragma unroll
                    for (int j = 0; j < 10; j++) {
                        const float4* vwp = reinterpret_cast<const float4*>(S->vW + j * 256 + g * 8);
                        float4 w0 = vwp[0], w1 = vwp[1];   // warp-uniform broadcast
                        float t0 = S->vb[j * 32 + g];
                        float a  = t0, a2 = t0;
                        a  += w0.x*xv[0] + w0.y*xv[1] + w0.z*xv[2] + w0.w*xv[3]
                            + w1.x*xv[4] + w1.y*xv[5] + w1.z*xv[6] + w1.w*xv[7];
                        a2 += w0.x*xv2[0] + w0.y*xv2[1] + w0.z*xv2[2] + w0.w*xv2[3]
                            + w1.x*xv2[4] + w1.y*xv2[5] + w1.z*xv2[6] + w1.w*xv2[7];
                        bb[j] = a; bb2[j] = a2;
                    }
                    float Z = 0.f, Z2 = 0.f;
                    #pragma unroll
                    for (int j = 0; j < 10; j++) {
                        bb[j]  = ex2_approx(bb[j]);   Z  += bb[j];
                        bb2[j] = ex2_approx(bb2[j]);  Z2 += bb2[j];
                    }
                    float r  = rcp_approx(Z);
                    float r2 = rcp_approx(Z2);
                    float* cw = S->cbuf + w * 360;
                    #pragma unroll
                    for (int j = 0; j < 10; j++) {
                        cw[j * 36 + lane] = bb[j] * r;
                        if (lane < 4) cw[j * 36 + 32 + lane] = bb2[j] * r2;
                    }
                }
                __syncwarp();
                // --- Phase B: cx[j][g][k] = sum_hw c*x ; csum[j][g] = sum_hw c ---
                {
                    const int k = lane >> 2, q = lane & 3;
                    const float* xr = S->x + (g * 8 + k) * 36;
                    float4 x0 = *reinterpret_cast<const float4*>(xr + 4 * q);
                    float4 x1 = *reinterpret_cast<const float4*>(xr + 16 + 4 * q);
                    float  x2 = xr[32 + q];
                    const float* cb = S->cbuf + w * 360;
                    float acc[10], cs[10];
                    #pragma unroll
                    for (int j = 0; j < 10; j++) {
                        float4 c0 = *reinterpret_cast<const float4*>(cb + j * 36 + 4 * q);
                        float4 c1 = *reinterpret_cast<const float4*>(cb + j * 36 + 16 + 4 * q);
                        float  c2 = cb[j * 36 + 32 + q];
                        acc[j] = dot4(c0, x0) + dot4(c1, x1) + c2 * x2;
                        cs[j]  = sum4(c0) + sum4(c1) + c2;
                    }
                    #pragma unroll
                    for (int j = 0; j < 10; j++) {
                        acc[j] += __shfl_xor_sync(0xffffffffu, acc[j], 1);
                        acc[j] += __shfl_xor_sync(0xffffffffu, acc[j], 2);
                        cs[j]  += __shfl_xor_sync(0xffffffffu, cs[j], 1);
                        cs[j]  += __shfl_xor_sync(0xffffffffu, cs[j], 2);
                    }
                    if (q == 0) {
                        #pragma unroll
                        for (int j = 0; j < 10; j++) S->cx[j * 256 + g * 8 + k] = acc[j];
                        if (k == 0) {
                            #pragma unroll
                            for (int j = 0; j < 10; j++) S->csum[j * 32 + g] = cs[j];
                        }
                    }
                }
                __syncwarp();
            }
            __syncthreads();
        }

        // ===== Phase C: sW[p] = sum_{g,k} W*cx (coalesced, 2 accumulators) =====
        if (tid < 320) {
            const int p  = tid >> 1;
            const int kh = tid & 1;
            const int j  = p >> 4;
            const float4* Wv  = reinterpret_cast<const float4*>(W);
            const float4* cxv = reinterpret_cast<const float4*>(S->cx);
            float acc0 = 0.f, acc1 = 0.f;
            #pragma unroll 8
            for (int g = 0; g < 32; g += 2) {
                acc0 += dot4(Wv[g * 320 + p * 2 + kh],       cxv[j * 64 + g * 2 + kh]);
                acc1 += dot4(Wv[(g + 1) * 320 + p * 2 + kh], cxv[j * 64 + (g + 1) * 2 + kh]);
            }
            float acc = acc0 + acc1;
            acc += __shfl_xor_sync(0xffffffffu, acc, 1);
            if (kh == 0) S->sW[p] = acc;
        } else {
            // bias part on warps 11-15: thread per pair (coalesced in p)
            const int p = tid - 352;
            if (p >= 0) {
                const int j = p >> 4;
                const float4* cs4 = reinterpret_cast<const float4*>(S->csum + j * 32);
                float accb = 0.f;
                #pragma unroll
                for (int gg = 0; gg < 8; gg++) {
                    float4 c4 = cs4[gg];
                    accb += bias[(gg * 4 + 0) * 160 + p] * c4.x
                          + bias[(gg * 4 + 1) * 160 + p] * c4.y
                          + bias[(gg * 4 + 2) * 160 + p] * c4.z
                          + bias[(gg * 4 + 3) * 160 + p] * c4.w;
                }
                S->sB[p] = accb;
            }
        }
        __syncthreads();

        // ===== Phase D: squash =====
        if (tid < 160) {
            const int p = tid;
            float sv = S->sW[p] + S->sB[p];
            float n2 = sv * sv;
            n2 += __shfl_xor_sync(0xffffffffu, n2, 1);
            n2 += __shfl_xor_sync(0xffffffffu, n2, 2);
            n2 += __shfl_xor_sync(0xffffffffu, n2, 4);
            n2 += __shfl_xor_sync(0xffffffffu, n2, 8);
            float f  = __fdividef(sqrtf(n2), 1.0f + n2);
            float vv = sv * f;
            S->v[p] = vv;
            if (it == 2) out[(size_t)b * 160 + p] = vv;
        }

        if (it < 2) {
            __syncthreads();
            // ===== Phase E: warp-per-tile, coalesced W/bias, shuffle reduce =====
            // 352 jobs: 0..319 -> vW tile (j = job>>5, g = job&31);
            //           320..351 -> vb group (g = job-320). 22 jobs/warp.
            const float4* Wv = reinterpret_cast<const float4*>(W);
            const float4* Bv = reinterpret_cast<const float4*>(bias);
            const float4* vv4 = reinterpret_cast<const float4*>(S->v);
            for (int t = 0; t < 22; t++) {
                const int job = w * 22 + t;
                if (job < 320) {
                    const int j = job >> 5, g = job & 31;
                    // lane l: floats [g*1280 + j*128 + 4l .. +3] -> d = l>>1, kh = l&1
                    float4 f4 = Wv[g * 320 + j * 32 + lane];
                    float  vd = S->v[j * 16 + (lane >> 1)];
                    float4 p4;
                    p4.x = f4.x * vd; p4.y = f4.y * vd;
                    p4.z = f4.z * vd; p4.w = f4.w * vd;
                    #pragma unroll
                    for (int m = 2; m <= 16; m <<= 1) {
                        p4.x += __shfl_xor_sync(0xffffffffu, p4.x, m);
                        p4.y += __shfl_xor_sync(0xffffffffu, p4.y, m);
                        p4.z += __shfl_xor_sync(0xffffffffu, p4.z, m);
                        p4.w += __shfl_xor_sync(0xffffffffu, p4.w, m);
                    }
                    if (lane < 2) {
                        float4 r;
                        r.x = p4.x * LOG2E; r.y = p4.y * LOG2E;
                        r.z = p4.z * LOG2E; r.w = p4.w * LOG2E;
                        float4* dst = reinterpret_cast<float4*>(S->vW) + j * 64 + g * 2 + lane;
                        if (it) {
                            float4 o = *dst;
                            r.x += o.x; r.y += o.y; r.z += o.z; r.w += o.w;
                        }
                        *dst = r;
                    }
                } else {
                    const int g = job - 320;
                    // part A: j = 0..7 (lane l: j = l>>2, c = l&3)
                    float4 fa = Bv[g * 40 + lane];
                    float4 va = vv4[lane];
                    float pa = dot4(fa, va);
                    // part B: j = 8,9 on lanes 0..7 (others compute dummy)
                    float4 fb = Bv[g * 40 + 32 + (lane & 7)];
                    float4 vb4 = vv4[32 + (lane & 7)];
                    float pb = dot4(fb, vb4);
                    pa += __shfl_xor_sync(0xffffffffu, pa, 1);
                    pa += __shfl_xor_sync(0xffffffffu, pa, 2);
                    pb += __shfl_xor_sync(0xffffffffu, pb, 1);
                    pb += __shfl_xor_sync(0xffffffffu, pb, 2);
                    if ((lane & 3) == 0) {
                        const int j = lane >> 2;
                        float val = pa * LOG2E;
                        if (it) val += S->vb[j * 32 + g];
                        S->vb[j * 32 + g] = val;
                        if (lane < 8) {
                            const int j2 = 8 + (lane >> 2);
                            float val2 = pb * LOG2E;
                            if (it) val2 += S->vb[j2 * 32 + g];
                            S->vb[j2 * 32 + g] = val2;
                        }
                    }
                }
            }
            __syncthreads();
        }
    }
}

extern "C" void kernel_launch(void* const* d_in, const int* in_sizes, int n_in,
                              void* d_out, int out_size) {
    const float* x    = (const float*)d_in[0];
    const float* W    = (const float*)d_in[2];
    const float* bias = (const float*)d_in[3];
    float* out = (float*)d_out;

    cudaFuncSetAttribute(caps_kernel,
                         cudaFuncAttributeMaxDynamicSharedMemorySize,
                         (int)sizeof(Smem));
    caps_kernel<<<512, 512, sizeof(Smem)>>>(x, W, bias, out);
}

// round 7
// speedup vs baseline: 1.1081x; 1.1081x over previous
#include <cuda_runtime.h>

// CapLayer fused capsule routing. 512 threads/CTA, 2 CTAs/SM.
// Telescoped routing logits: b = (sum_it v_it) dot pred, so vW/vb are computed
// on the fly in Phase A from vsum (160 floats) -- no Phase E pass at all.
// x:    d_in[0]  float [512][256][6][6]   (channel = g*8+k, g<32, k<8)
// W:    d_in[2]  float [5120][8] ; flat = g*1280 + j*128 + d*8 + k
// bias: d_in[3]  float [5120]    ; flat = g*160  + j*16  + d
// out:  float [512][10][16]

#define LOG2E 1.4426950408889634f

struct Smem {
    float x[9216];        // [g][k][hw]
    float cbuf[16 * 360]; // per-warp c scratch [w][j][hw]
    float scr[16 * 96];   // per-warp: [0..79] vW[j][k], [80..89] vb[j]
    float cx[2560];       // [j][g][k]
    float csum[320];      // [j][g]
    float sWsB[320];      // sW=[0..159], sB=[160..319]; xsum aliases [0..255] at init
    float vsum[160];      // LOG2E * sum of past v's, [j][d]
};                        // 19872 floats = 79488 B (2 CTAs/SM: 159KB)

__device__ __forceinline__ float ex2_approx(float x) {
    float y; asm("ex2.approx.ftz.f32 %0, %1;" : "=f"(y) : "f"(x)); return y;
}
__device__ __forceinline__ float rcp_approx(float x) {
    float y; asm("rcp.approx.ftz.f32 %0, %1;" : "=f"(y) : "f"(x)); return y;
}
__device__ __forceinline__ float dot4(float4 a, float4 b) {
    return a.x * b.x + a.y * b.y + a.z * b.z + a.w * b.w;
}
__device__ __forceinline__ float sum4(float4 a) {
    return a.x + a.y + a.z + a.w;
}

__global__ __launch_bounds__(512, 2)
void caps_kernel(const float* __restrict__ x_g,
                 const float* __restrict__ W,
                 const float* __restrict__ bias,
                 float* __restrict__ out) {
    extern __shared__ float smem_raw[];
    Smem* S = reinterpret_cast<Smem*>(smem_raw);

    const int b    = blockIdx.x;
    const int tid  = threadIdx.x;
    const int w    = tid >> 5;
    const int lane = tid & 31;

    // ---- load x ([g][k][hw] contiguous) ----
    {
        const float4* src = reinterpret_cast<const float4*>(x_g + (size_t)b * 9216);
        float4* dst = reinterpret_cast<float4*>(S->x);
        #pragma unroll
        for (int i = 0; i < 5; i++) {
            int idx = tid + i * 512;
            if (idx < 2304) dst[idx] = src[idx];
        }
    }
    __syncthreads();

    // ---- xsum[g][k] = sum_hw x (stored in sWsB alias region) ----
    if (tid < 256) {
        const float4* p = reinterpret_cast<const float4*>(S->x + tid * 36);
        float4 a4 = p[0];
        #pragma unroll
        for (int t = 1; t < 9; t++) {
            float4 q = p[t];
            a4.x += q.x; a4.y += q.y; a4.z += q.z; a4.w += q.w;
        }
        S->sWsB[tid] = sum4(a4);
    }
    __syncthreads();

    // iter 1 shortcut: c uniform 0.1 -> cx = 0.1*xsum (all j), csum = 3.6
    for (int i = tid; i < 2560; i += 512) S->cx[i] = 0.1f * S->sWsB[i & 255];
    if (tid < 320) S->csum[tid] = 3.6f;
    __syncthreads();

    for (int it = 0; it < 3; ++it) {
        if (it > 0) {
            // ===== Phase A+B per warp; warp handles groups w and w+16 =====
            #pragma unroll
            for (int gi = 0; gi < 2; gi++) {
                const int g = w + gi * 16;
                float* scr = S->scr + w * 96;

                // --- A-pre: vW[j][k] = sum_d vsum[j][d]*W[g,j,d,k]; vb[j] likewise ---
                {
                    const float4* Wv = reinterpret_cast<const float4*>(W);
                    const float*  vs = S->vsum;
                    #pragma unroll
                    for (int j = 0; j < 10; j++) {
                        float4 f4 = Wv[g * 320 + j * 32 + lane]; // coalesced 512B
                        float  vd = vs[j * 16 + (lane >> 1)];
                        float4 p4;
                        p4.x = f4.x * vd; p4.y = f4.y * vd;
                        p4.z = f4.z * vd; p4.w = f4.w * vd;
                        #pragma unroll
                        for (int m = 2; m <= 16; m <<= 1) {  // reduce over d (kh kept)
                            p4.x += __shfl_xor_sync(0xffffffffu, p4.x, m);
                            p4.y += __shfl_xor_sync(0xffffffffu, p4.y, m);
                            p4.z += __shfl_xor_sync(0xffffffffu, p4.z, m);
                            p4.w += __shfl_xor_sync(0xffffffffu, p4.w, m);
                        }
                        if (lane < 2)
                            reinterpret_cast<float4*>(scr + j * 8)[lane] = p4;
                    }
                    // vb: bias[g] block = 160 contiguous floats
                    const float4* Bv  = reinterpret_cast<const float4*>(bias);
                    const float4* vs4 = reinterpret_cast<const float4*>(vs);
                    float4 fa  = Bv[g * 40 + lane];
                    float4 va  = vs4[lane];
                    float  pa  = dot4(fa, va);
                    float4 fb  = Bv[g * 40 + 32 + (lane & 7)];
                    float4 vb4 = vs4[32 + (lane & 7)];
                    float  pb  = dot4(fb, vb4);
                    pa += __shfl_xor_sync(0xffffffffu, pa, 1);
                    pa += __shfl_xor_sync(0xffffffffu, pa, 2);
                    pb += __shfl_xor_sync(0xffffffffu, pb, 1);
                    pb += __shfl_xor_sync(0xffffffffu, pb, 2);
                    if ((lane & 3) == 0) {
                        scr[80 + (lane >> 2)] = pa;             // j = 0..7
                        if (lane < 8) scr[88 + (lane >> 2)] = pb; // j = 8,9
                    }
                }
                __syncwarp();

                // --- Phase A: logits -> softmax over j -> c (per-warp buffer) ---
                {
                    const float* xr = S->x + g * 8 * 36;
                    float xv[8], xv2[8];
                    #pragma unroll
                    for (int k = 0; k < 8; k++) {
                        xv[k]  = xr[k * 36 + lane];
                        xv2[k] = xr[k * 36 + 32 + (lane & 3)];
                    }
                    float bb[10], bb2[10];
                    #pragma unroll
                    for (int j = 0; j < 10; j++) {
                        const float4* vwp = reinterpret_cast<const float4*>(scr + j * 8);
                        float4 w0 = vwp[0], w1 = vwp[1];   // warp-uniform broadcast
                        float t0 = scr[80 + j];
                        float a  = t0, a2 = t0;
                        a  += w0.x*xv[0] + w0.y*xv[1] + w0.z*xv[2] + w0.w*xv[3]
                            + w1.x*xv[4] + w1.y*xv[5] + w1.z*xv[6] + w1.w*xv[7];
                        a2 += w0.x*xv2[0] + w0.y*xv2[1] + w0.z*xv2[2] + w0.w*xv2[3]
                            + w1.x*xv2[4] + w1.y*xv2[5] + w1.z*xv2[6] + w1.w*xv2[7];
                        bb[j] = a; bb2[j] = a2;
                    }
                    float Z = 0.f, Z2 = 0.f;
                    #pragma unroll
                    for (int j = 0; j < 10; j++) {
                        bb[j]  = ex2_approx(bb[j]);   Z  += bb[j];
                        bb2[j] = ex2_approx(bb2[j]);  Z2 += bb2[j];
                    }
                    float r  = rcp_approx(Z);
                    float r2 = rcp_approx(Z2);
                    float* cw = S->cbuf + w * 360;
                    #pragma unroll
                    for (int j = 0; j < 10; j++) {
                        cw[j * 36 + lane] = bb[j] * r;
                        if (lane < 4) cw[j * 36 + 32 + lane] = bb2[j] * r2;
                    }
                }
                __syncwarp();

                // --- Phase B: cx[j][g][k] = sum_hw c*x ; csum[j][g] = sum_hw c ---
                {
                    const int k = lane >> 2, q = lane & 3;
                    const float* xr = S->x + (g * 8 + k) * 36;
                    float4 x0 = *reinterpret_cast<const float4*>(xr + 4 * q);
                    float4 x1 = *reinterpret_cast<const float4*>(xr + 16 + 4 * q);
                    float  x2 = xr[32 + q];
                    const float* cb = S->cbuf + w * 360;
                    float acc[10], cs[10];
                    #pragma unroll
                    for (int j = 0; j < 10; j++) {
                        float4 c0 = *reinterpret_cast<const float4*>(cb + j * 36 + 4 * q);
                        float4 c1 = *reinterpret_cast<const float4*>(cb + j * 36 + 16 + 4 * q);
                        float  c2 = cb[j * 36 + 32 + q];
                        acc[j] = dot4(c0, x0) + dot4(c1, x1) + c2 * x2;
                        cs[j]  = sum4(c0) + sum4(c1) + c2;
                    }
                    #pragma unroll
                    for (int j = 0; j < 10; j++) {
                        acc[j] += __shfl_xor_sync(0xffffffffu, acc[j], 1);
                        acc[j] += __shfl_xor_sync(0xffffffffu, acc[j], 2);
                        cs[j]  += __shfl_xor_sync(0xffffffffu, cs[j], 1);
                        cs[j]  += __shfl_xor_sync(0xffffffffu, cs[j], 2);
                    }
                    if (q == 0) {
                        #pragma unroll
                        for (int j = 0; j < 10; j++) S->cx[j * 256 + g * 8 + k] = acc[j];
                        if (k == 0) {
                            #pragma unroll
                            for (int j = 0; j < 10; j++) S->csum[j * 32 + g] = cs[j];
                        }
                    }
                }
                __syncwarp();
            }
            __syncthreads();
        }

        // ===== Phase C: sW[p] = sum_{g,k} W*cx (coalesced, 2 accumulators) =====
        if (tid < 320) {
            const int p  = tid >> 1;
            const int kh = tid & 1;
            const int j  = p >> 4;
            const float4* Wv  = reinterpret_cast<const float4*>(W);
            const float4* cxv = reinterpret_cast<const float4*>(S->cx);
            float acc0 = 0.f, acc1 = 0.f;
            #pragma unroll 8
            for (int g = 0; g < 32; g += 2) {
                acc0 += dot4(Wv[g * 320 + p * 2 + kh],       cxv[j * 64 + g * 2 + kh]);
                acc1 += dot4(Wv[(g + 1) * 320 + p * 2 + kh], cxv[j * 64 + (g + 1) * 2 + kh]);
            }
            float acc = acc0 + acc1;
            acc += __shfl_xor_sync(0xffffffffu, acc, 1);
            if (kh == 0) S->sWsB[p] = acc;
        } else {
            // bias part on warps 11-15: thread per pair (coalesced in p)
            const int p = tid - 352;
            if (p >= 0) {
                const int j = p >> 4;
                const float4* cs4 = reinterpret_cast<const float4*>(S->csum + j * 32);
                float accb = 0.f;
                #pragma unroll
                for (int gg = 0; gg < 8; gg++) {
                    float4 c4 = cs4[gg];
                    accb += bias[(gg * 4 + 0) * 160 + p] * c4.x
                          + bias[(gg * 4 + 1) * 160 + p] * c4.y
                          + bias[(gg * 4 + 2) * 160 + p] * c4.z
                          + bias[(gg * 4 + 3) * 160 + p] * c4.w;
                }
                S->sWsB[160 + p] = accb;
            }
        }
        __syncthreads();

        // ===== Phase D: squash + telescoped accumulate vsum += LOG2E*v =====
        if (tid < 160) {
            const int p = tid;
            float sv = S->sWsB[p] + S->sWsB[160 + p];
            float n2 = sv * sv;
            n2 += __shfl_xor_sync(0xffffffffu, n2, 1);
            n2 += __shfl_xor_sync(0xffffffffu, n2, 2);
            n2 += __shfl_xor_sync(0xffffffffu, n2, 4);
            n2 += __shfl_xor_sync(0xffffffffu, n2, 8);
            float f  = __fdividef(sqrtf(n2), 1.0f + n2);
            float vv = sv * f;
            if (it == 2) {
                out[(size_t)b * 160 + p] = vv;
            } else {
                S->vsum[p] = (it == 0) ? LOG2E * vv : S->vsum[p] + LOG2E * vv;
            }
        }
        if (it < 2) __syncthreads();
    }
}

extern "C" void kernel_launch(void* const* d_in, const int* in_sizes, int n_in,
                              void* d_out, int out_size) {
    const float* x    = (const float*)d_in[0];
    const float* W    = (const float*)d_in[2];
    const float* bias = (const float*)d_in[3];
    float* out = (float*)d_out;

    cudaFuncSetAttribute(caps_kernel,
                         cudaFuncAttributeMaxDynamicSharedMemorySize,
                         (int)sizeof(Smem));
    caps_kernel<<<512, 512, sizeof(Smem)>>>(x, W, bias, out);
}

// round 8
// speedup vs baseline: 1.3053x; 1.1779x over previous
#include <cuda_runtime.h>

// CapLayer fused capsule routing. 512 threads/CTA, 2 CTAs/SM.
// Pre-kernel transposes W -> WT[g][j][k][d] (d contiguous) so the per-group
// vW = vsum . W reduction in Phase A-pre is coalesced with no shuffle tree.
// x:    d_in[0]  float [512][256][6][6]   (channel = g*8+k, g<32, k<8)
// W:    d_in[2]  float [5120][8] ; flat = g*1280 + j*128 + d*8 + k
// bias: d_in[3]  float [5120]    ; flat = g*160  + j*16  + d
// out:  float [512][10][16]

#define LOG2E 1.4426950408889634f

__device__ float g_WT[40960];   // [g][j][k][d]

struct Smem {
    float x[9216];        // [g][k][hw]
    float cbuf[16 * 360]; // per-warp c scratch [w][j][hw]
    float scr[16 * 96];   // per-warp: [0..79] vW[j][k] (k contig), [80..89] vb[j]
    float cx[2560];       // [j][g][k]
    float csum[320];      // [j][g]
    float sWsB[320];      // sW=[0..159], sB=[160..319]; xsum aliases [0..255] at init
    float vsum[160];      // LOG2E * sum of past v's, [j][d]
};                        // 19872 floats = 79488 B (2 CTAs/SM)

__device__ __forceinline__ float ex2_approx(float x) {
    float y; asm("ex2.approx.ftz.f32 %0, %1;" : "=f"(y) : "f"(x)); return y;
}
__device__ __forceinline__ float rcp_approx(float x) {
    float y; asm("rcp.approx.ftz.f32 %0, %1;" : "=f"(y) : "f"(x)); return y;
}
__device__ __forceinline__ float dot4(float4 a, float4 b) {
    return a.x * b.x + a.y * b.y + a.z * b.z + a.w * b.w;
}
__device__ __forceinline__ float sum4(float4 a) {
    return a.x + a.y + a.z + a.w;
}

__global__ void transpose_W_kernel(const float* __restrict__ W) {
    int i = blockIdx.x * 256 + threadIdx.x;      // output index
    if (i < 40960) {
        int d = i & 15;
        int k = (i >> 4) & 7;
        int gj = i >> 7;                          // g*10 + j
        int j = gj % 10, g = gj / 10;
        g_WT[i] = W[g * 1280 + j * 128 + d * 8 + k];
    }
}

__global__ __launch_bounds__(512, 2)
void caps_kernel(const float* __restrict__ x_g,
                 const float* __restrict__ W,
                 const float* __restrict__ bias,
                 float* __restrict__ out) {
    extern __shared__ float smem_raw[];
    Smem* S = reinterpret_cast<Smem*>(smem_raw);

    const int b    = blockIdx.x;
    const int tid  = threadIdx.x;
    const int w    = tid >> 5;
    const int lane = tid & 31;

    // ---- load x ([g][k][hw] contiguous) ----
    {
        const float4* src = reinterpret_cast<const float4*>(x_g + (size_t)b * 9216);
        float4* dst = reinterpret_cast<float4*>(S->x);
        #pragma unroll
        for (int i = 0; i < 5; i++) {
            int idx = tid + i * 512;
            if (idx < 2304) dst[idx] = src[idx];
        }
    }
    __syncthreads();

    // ---- xsum[g][k] = sum_hw x (stored in sWsB alias region) ----
    if (tid < 256) {
        const float4* p = reinterpret_cast<const float4*>(S->x + tid * 36);
        float4 a4 = p[0];
        #pragma unroll
        for (int t = 1; t < 9; t++) {
            float4 q = p[t];
            a4.x += q.x; a4.y += q.y; a4.z += q.z; a4.w += q.w;
        }
        S->sWsB[tid] = sum4(a4);
    }
    __syncthreads();

    // iter 1 shortcut: c uniform 0.1 -> cx = 0.1*xsum (all j), csum = 3.6
    for (int i = tid; i < 2560; i += 512) S->cx[i] = 0.1f * S->sWsB[i & 255];
    if (tid < 320) S->csum[tid] = 3.6f;
    __syncthreads();

    for (int it = 0; it < 3; ++it) {
        if (it > 0) {
            // ===== Phase A+B per warp; warp handles groups w and w+16 =====
            #pragma unroll
            for (int gi = 0; gi < 2; gi++) {
                const int g = w + gi * 16;
                float* scr = S->scr + w * 96;

                // --- A-pre: vW[j][k] = sum_d vsum[j][d]*WT[g,j,k,d] (coalesced) ---
                {
                    const float4* WTv = reinterpret_cast<const float4*>(g_WT) + g * 320;
                    const float4* vs4 = reinterpret_cast<const float4*>(S->vsum);
                    const int q  = lane & 3;    // d-quad
                    const int jk = lane >> 2;   // k index within round (round = j)
                    #pragma unroll
                    for (int r = 0; r < 10; r++) {
                        float4 a  = WTv[r * 32 + lane];   // consecutive float4s: 512B/instr
                        float4 bq = vs4[r * 4 + q];
                        float part = dot4(a, bq);
                        part += __shfl_xor_sync(0xffffffffu, part, 1);
                        part += __shfl_xor_sync(0xffffffffu, part, 2);
                        if (q == 0) scr[r * 8 + jk] = part;
                    }
                    // vb[j] = sum_d vsum[j][d]*bias[g,j,d] (contiguous bias block)
                    const float4* Bv  = reinterpret_cast<const float4*>(bias);
                    float4 fa  = Bv[g * 40 + lane];
                    float4 va  = vs4[lane];
                    float  pa  = dot4(fa, va);
                    float4 fb  = Bv[g * 40 + 32 + (lane & 7)];
                    float4 vb4 = vs4[32 + (lane & 7)];
                    float  pb  = dot4(fb, vb4);
                    pa += __shfl_xor_sync(0xffffffffu, pa, 1);
                    pa += __shfl_xor_sync(0xffffffffu, pa, 2);
                    pb += __shfl_xor_sync(0xffffffffu, pb, 1);
                    pb += __shfl_xor_sync(0xffffffffu, pb, 2);
                    if ((lane & 3) == 0) {
                        scr[80 + (lane >> 2)] = pa;               // j = 0..7
                        if (lane < 8) scr[88 + (lane >> 2)] = pb; // j = 8,9
                    }
                }
                __syncwarp();

                // --- Phase A: logits -> softmax over j -> c (per-warp buffer) ---
                {
                    const float* xr = S->x + g * 8 * 36;
                    float xv[8], xv2[8];
                    #pragma unroll
                    for (int k = 0; k < 8; k++) {
                        xv[k]  = xr[k * 36 + lane];
                        xv2[k] = xr[k * 36 + 32 + (lane & 3)];
                    }
                    float bb[10], bb2[10];
                    #pragma unroll
                    for (int j = 0; j < 10; j++) {
                        const float4* vwp = reinterpret_cast<const float4*>(scr + j * 8);
                        float4 w0 = vwp[0], w1 = vwp[1];   // warp-uniform broadcast
                        float t0 = scr[80 + j];
                        float a  = t0, a2 = t0;
                        a  += w0.x*xv[0] + w0.y*xv[1] + w0.z*xv[2] + w0.w*xv[3]
                            + w1.x*xv[4] + w1.y*xv[5] + w1.z*xv[6] + w1.w*xv[7];
                        a2 += w0.x*xv2[0] + w0.y*xv2[1] + w0.z*xv2[2] + w0.w*xv2[3]
                            + w1.x*xv2[4] + w1.y*xv2[5] + w1.z*xv2[6] + w1.w*xv2[7];
                        bb[j] = a; bb2[j] = a2;
                    }
                    float Z = 0.f, Z2 = 0.f;
                    #pragma unroll
                    for (int j = 0; j < 10; j++) {
                        bb[j]  = ex2_approx(bb[j]);   Z  += bb[j];
                        bb2[j] = ex2_approx(bb2[j]);  Z2 += bb2[j];
                    }
                    float r  = rcp_approx(Z);
                    float r2 = rcp_approx(Z2);
                    float* cw = S->cbuf + w * 360;
                    #pragma unroll
                    for (int j = 0; j < 10; j++) {
                        cw[j * 36 + lane] = bb[j] * r;
                        if (lane < 4) cw[j * 36 + 32 + lane] = bb2[j] * r2;
                    }
                }
                __syncwarp();

                // --- Phase B: cx[j][g][k] = sum_hw c*x ; csum[j][g] = sum_hw c ---
                {
                    const int k = lane >> 2, q = lane & 3;
                    const float* xr = S->x + (g * 8 + k) * 36;
                    float4 x0 = *reinterpret_cast<const float4*>(xr + 4 * q);
                    float4 x1 = *reinterpret_cast<const float4*>(xr + 16 + 4 * q);
                    float  x2 = xr[32 + q];
                    const float* cb = S->cbuf + w * 360;
                    float acc[10], cs[10];
                    #pragma unroll
                    for (int j = 0; j < 10; j++) {
                        float4 c0 = *reinterpret_cast<const float4*>(cb + j * 36 + 4 * q);
                        float4 c1 = *reinterpret_cast<const float4*>(cb + j * 36 + 16 + 4 * q);
                        float  c2 = cb[j * 36 + 32 + q];
                        acc[j] = dot4(c0, x0) + dot4(c1, x1) + c2 * x2;
                        cs[j]  = sum4(c0) + sum4(c1) + c2;
                    }
                    #pragma unroll
                    for (int j = 0; j < 10; j++) {
                        acc[j] += __shfl_xor_sync(0xffffffffu, acc[j], 1);
                        acc[j] += __shfl_xor_sync(0xffffffffu, acc[j], 2);
                        cs[j]  += __shfl_xor_sync(0xffffffffu, cs[j], 1);
                        cs[j]  += __shfl_xor_sync(0xffffffffu, cs[j], 2);
                    }
                    if (q == 0) {
                        #pragma unroll
                        for (int j = 0; j < 10; j++) S->cx[j * 256 + g * 8 + k] = acc[j];
                        if (k == 0) {
                            #pragma unroll
                            for (int j = 0; j < 10; j++) S->csum[j * 32 + g] = cs[j];
                        }
                    }
                }
                __syncwarp();
            }
            __syncthreads();
        }

        // ===== Phase C: sW[p] = sum_{g,k} W*cx (coalesced, 2 accumulators) =====
        if (tid < 320) {
            const int p  = tid >> 1;
            const int kh = tid & 1;
            const int j  = p >> 4;
            const float4* Wv  = reinterpret_cast<const float4*>(W);
            const float4* cxv = reinterpret_cast<const float4*>(S->cx);
            float acc0 = 0.f, acc1 = 0.f;
            #pragma unroll 8
            for (int g = 0; g < 32; g += 2) {
                acc0 += dot4(Wv[g * 320 + p * 2 + kh],       cxv[j * 64 + g * 2 + kh]);
                acc1 += dot4(Wv[(g + 1) * 320 + p * 2 + kh], cxv[j * 64 + (g + 1) * 2 + kh]);
            }
            float acc = acc0 + acc1;
            acc += __shfl_xor_sync(0xffffffffu, acc, 1);
            if (kh == 0) S->sWsB[p] = acc;
        } else {
            // bias part on warps 11-15: thread per pair (coalesced in p)
            const int p = tid - 352;
            if (p >= 0) {
                const int j = p >> 4;
                const float4* cs4 = reinterpret_cast<const float4*>(S->csum + j * 32);
                float accb = 0.f;
                #pragma unroll
                for (int gg = 0; gg < 8; gg++) {
                    float4 c4 = cs4[gg];
                    accb += bias[(gg * 4 + 0) * 160 + p] * c4.x
                          + bias[(gg * 4 + 1) * 160 + p] * c4.y
                          + bias[(gg * 4 + 2) * 160 + p] * c4.z
                          + bias[(gg * 4 + 3) * 160 + p] * c4.w;
                }
                S->sWsB[160 + p] = accb;
            }
        }
        __syncthreads();

        // ===== Phase D: squash + telescoped accumulate vsum += LOG2E*v =====
        if (tid < 160) {
            const int p = tid;
            float sv = S->sWsB[p] + S->sWsB[160 + p];
            float n2 = sv * sv;
            n2 += __shfl_xor_sync(0xffffffffu, n2, 1);
            n2 += __shfl_xor_sync(0xffffffffu, n2, 2);
            n2 += __shfl_xor_sync(0xffffffffu, n2, 4);
            n2 += __shfl_xor_sync(0xffffffffu, n2, 8);
            float f  = __fdividef(sqrtf(n2), 1.0f + n2);
            float vv = sv * f;
            if (it == 2) {
                out[(size_t)b * 160 + p] = vv;
            } else {
                S->vsum[p] = (it == 0) ? LOG2E * vv : S->vsum[p] + LOG2E * vv;
            }
        }
        if (it < 2) __syncthreads();
    }
}

extern "C" void kernel_launch(void* const* d_in, const int* in_sizes, int n_in,
                              void* d_out, int out_size) {
    const float* x    = (const float*)d_in[0];
    const float* W    = (const float*)d_in[2];
    const float* bias = (const float*)d_in[3];
    float* out = (float*)d_out;

    transpose_W_kernel<<<160, 256>>>(W);

    cudaFuncSetAttribute(caps_kernel,
                         cudaFuncAttributeMaxDynamicSharedMemorySize,
                         (int)sizeof(Smem));
    caps_kernel<<<512, 512, sizeof(Smem)>>>(x, W, bias, out);
}

// round 9
// speedup vs baseline: 1.3900x; 1.0649x over previous
#include <cuda_runtime.h>

// CapLayer fused capsule routing. 256 CTAs x 1024 threads, 2 batch elems/CTA.
// Weight streams (W, WT, bias) are loaded once per CTA and shared by both
// elements, halving per-element global traffic.
// x:    d_in[0]  float [512][256][6][6]   (channel = g*8+k, g<32, k<8)
// W:    d_in[2]  float [5120][8] ; flat = g*1280 + j*128 + d*8 + k
// bias: d_in[3]  float [5120]    ; flat = g*160  + j*16  + d
// out:  float [512][10][16]

#define LOG2E 1.4426950408889634f

__device__ float g_WT[40960];   // [g][j][k][d]

struct Smem {
    float x[2][9216];     // [e][g][k][hw]
    float cbuf[32][360];  // per-warp c scratch [w][j][hw]
    float scr[32][192];   // per-warp, per-elem 96: [0..79] vW[j][k], [80..89] vb[j]
    float cx[2][2560];    // [e][j][g][k]
    float csum[2][320];   // [e][j][g]
    float sWsB[2][320];   // sW=[0..159], sB=[160..319]; xsum aliases [0..255]
    float vsum[2][160];   // LOG2E * accumulated v, [e][j][d]
};                        // 42816 floats = 171264 B (1 CTA/SM)

__device__ __forceinline__ float ex2_approx(float x) {
    float y; asm("ex2.approx.ftz.f32 %0, %1;" : "=f"(y) : "f"(x)); return y;
}
__device__ __forceinline__ float rcp_approx(float x) {
    float y; asm("rcp.approx.ftz.f32 %0, %1;" : "=f"(y) : "f"(x)); return y;
}
__device__ __forceinline__ float dot4(float4 a, float4 b) {
    return a.x * b.x + a.y * b.y + a.z * b.z + a.w * b.w;
}
__device__ __forceinline__ float sum4(float4 a) {
    return a.x + a.y + a.z + a.w;
}

__global__ void transpose_W_kernel(const float* __restrict__ W) {
    int i = blockIdx.x * 256 + threadIdx.x;
    if (i < 40960) {
        int d = i & 15;
        int k = (i >> 4) & 7;
        int gj = i >> 7;
        int j = gj % 10, g = gj / 10;
        g_WT[i] = W[g * 1280 + j * 128 + d * 8 + k];
    }
}

__global__ __launch_bounds__(1024, 1)
void caps_kernel(const float* __restrict__ x_g,
                 const float* __restrict__ W,
                 const float* __restrict__ bias,
                 float* __restrict__ out) {
    extern __shared__ float smem_raw[];
    Smem* S = reinterpret_cast<Smem*>(smem_raw);

    const int b0   = blockIdx.x * 2;
    const int tid  = threadIdx.x;
    const int w    = tid >> 5;     // warp = group (32 warps, 32 groups)
    const int lane = tid & 31;

    // ---- load x for both elements (contiguous 18432 floats) ----
    {
        const float4* src = reinterpret_cast<const float4*>(x_g + (size_t)b0 * 9216);
        float4* dst = reinterpret_cast<float4*>(&S->x[0][0]);
        #pragma unroll
        for (int i = 0; i < 5; i++) {
            int idx = tid + i * 1024;
            if (idx < 4608) dst[idx] = src[idx];
        }
    }
    __syncthreads();

    // ---- xsum[e][g][k] = sum_hw x (stored in sWsB alias region) ----
    if (tid < 512) {
        const int e = tid >> 8, idx = tid & 255;
        const float4* p = reinterpret_cast<const float4*>(&S->x[e][0] + idx * 36);
        float4 a4 = p[0];
        #pragma unroll
        for (int t = 1; t < 9; t++) {
            float4 q = p[t];
            a4.x += q.x; a4.y += q.y; a4.z += q.z; a4.w += q.w;
        }
        S->sWsB[e][idx] = sum4(a4);
    }
    __syncthreads();

    // iter 1 shortcut: c uniform 0.1 -> cx = 0.1*xsum (all j), csum = 3.6
    for (int i = tid; i < 5120; i += 1024) {
        const int e = (i >= 2560);
        const int ii = i - e * 2560;
        S->cx[0][i] = 0.1f * S->sWsB[e][ii & 255];   // cx is [2][2560] contiguous
    }
    if (tid < 640) S->csum[0][tid] = 3.6f;           // both elems contiguous
    __syncthreads();

    for (int it = 0; it < 3; ++it) {
        if (it > 0) {
            const int g = w;
            float* scr = S->scr[w];

            // --- A-pre (shared weight loads for both elements) ---
            {
                const float4* WTv = reinterpret_cast<const float4*>(g_WT) + g * 320;
                const float4* vs0 = reinterpret_cast<const float4*>(S->vsum[0]);
                const float4* vs1 = reinterpret_cast<const float4*>(S->vsum[1]);
                const int q  = lane & 3;
                const int jk = lane >> 2;
                #pragma unroll
                for (int r = 0; r < 10; r++) {
                    float4 a = WTv[r * 32 + lane];           // coalesced 512B
                    float p0 = dot4(a, vs0[r * 4 + q]);
                    float p1 = dot4(a, vs1[r * 4 + q]);
                    p0 += __shfl_xor_sync(0xffffffffu, p0, 1);
                    p0 += __shfl_xor_sync(0xffffffffu, p0, 2);
                    p1 += __shfl_xor_sync(0xffffffffu, p1, 1);
                    p1 += __shfl_xor_sync(0xffffffffu, p1, 2);
                    if (q == 0) { scr[r * 8 + jk] = p0; scr[96 + r * 8 + jk] = p1; }
                }
                const float4* Bv = reinterpret_cast<const float4*>(bias);
                float4 fa = Bv[g * 40 + lane];
                float4 fb = Bv[g * 40 + 32 + (lane & 7)];
                float pa0 = dot4(fa, vs0[lane]);
                float pa1 = dot4(fa, vs1[lane]);
                float pb0 = dot4(fb, vs0[32 + (lane & 7)]);
                float pb1 = dot4(fb, vs1[32 + (lane & 7)]);
                pa0 += __shfl_xor_sync(0xffffffffu, pa0, 1);
                pa0 += __shfl_xor_sync(0xffffffffu, pa0, 2);
                pa1 += __shfl_xor_sync(0xffffffffu, pa1, 1);
                pa1 += __shfl_xor_sync(0xffffffffu, pa1, 2);
                pb0 += __shfl_xor_sync(0xffffffffu, pb0, 1);
                pb0 += __shfl_xor_sync(0xffffffffu, pb0, 2);
                pb1 += __shfl_xor_sync(0xffffffffu, pb1, 1);
                pb1 += __shfl_xor_sync(0xffffffffu, pb1, 2);
                if ((lane & 3) == 0) {
                    scr[80 + (lane >> 2)] = pa0;
                    scr[96 + 80 + (lane >> 2)] = pa1;
                    if (lane < 8) {
                        scr[88 + (lane >> 2)] = pb0;
                        scr[96 + 88 + (lane >> 2)] = pb1;
                    }
                }
            }
            __syncwarp();

            // --- Phase A+B per element (sequential in warp, cbuf reused) ---
            #pragma unroll
            for (int e = 0; e < 2; e++) {
                const float* se = scr + e * 96;
                // Phase A: logits -> softmax over j -> c
                {
                    const float* xr = &S->x[e][0] + g * 288;
                    float xv[8], xv2[8];
                    #pragma unroll
                    for (int k = 0; k < 8; k++) {
                        xv[k]  = xr[k * 36 + lane];
                        xv2[k] = xr[k * 36 + 32 + (lane & 3)];
                    }
                    float bb[10], bb2[10];
                    #pragma unroll
                    for (int j = 0; j < 10; j++) {
                        const float4* vwp = reinterpret_cast<const float4*>(se + j * 8);
                        float4 w0 = vwp[0], w1 = vwp[1];
                        float t0 = se[80 + j];
                        float a  = t0, a2 = t0;
                        a  += w0.x*xv[0] + w0.y*xv[1] + w0.z*xv[2] + w0.w*xv[3]
                            + w1.x*xv[4] + w1.y*xv[5] + w1.z*xv[6] + w1.w*xv[7];
                        a2 += w0.x*xv2[0] + w0.y*xv2[1] + w0.z*xv2[2] + w0.w*xv2[3]
                            + w1.x*xv2[4] + w1.y*xv2[5] + w1.z*xv2[6] + w1.w*xv2[7];
                        bb[j] = a; bb2[j] = a2;
                    }
                    float Z = 0.f, Z2 = 0.f;
                    #pragma unroll
                    for (int j = 0; j < 10; j++) {
                        bb[j]  = ex2_approx(bb[j]);   Z  += bb[j];
                        bb2[j] = ex2_approx(bb2[j]);  Z2 += bb2[j];
                    }
                    float r  = rcp_approx(Z);
                    float r2 = rcp_approx(Z2);
                    float* cw = S->cbuf[w];
                    #pragma unroll
                    for (int j = 0; j < 10; j++) {
                        cw[j * 36 + lane] = bb[j] * r;
                        if (lane < 4) cw[j * 36 + 32 + lane] = bb2[j] * r2;
                    }
                }
                __syncwarp();
                // Phase B: cx[e][j][g][k] = sum_hw c*x ; csum[e][j][g]
                {
                    const int k = lane >> 2, q = lane & 3;
                    const float* xr = &S->x[e][0] + (g * 8 + k) * 36;
                    float4 x0 = *reinterpret_cast<const float4*>(xr + 4 * q);
                    float4 x1 = *reinterpret_cast<const float4*>(xr + 16 + 4 * q);
                    float  x2 = xr[32 + q];
                    const float* cb = S->cbuf[w];
                    float acc[10], cs[10];
                    #pragma unroll
                    for (int j = 0; j < 10; j++) {
                        float4 c0 = *reinterpret_cast<const float4*>(cb + j * 36 + 4 * q);
                        float4 c1 = *reinterpret_cast<const float4*>(cb + j * 36 + 16 + 4 * q);
                        float  c2 = cb[j * 36 + 32 + q];
                        acc[j] = dot4(c0, x0) + dot4(c1, x1) + c2 * x2;
                        cs[j]  = sum4(c0) + sum4(c1) + c2;
                    }
                    #pragma unroll
                    for (int j = 0; j < 10; j++) {
                        acc[j] += __shfl_xor_sync(0xffffffffu, acc[j], 1);
                        acc[j] += __shfl_xor_sync(0xffffffffu, acc[j], 2);
                        cs[j]  += __shfl_xor_sync(0xffffffffu, cs[j], 1);
                        cs[j]  += __shfl_xor_sync(0xffffffffu, cs[j], 2);
                    }
                    if (q == 0) {
                        #pragma unroll
                        for (int j = 0; j < 10; j++) S->cx[e][j * 256 + g * 8 + k] = acc[j];
                        if (k == 0) {
                            #pragma unroll
                            for (int j = 0; j < 10; j++) S->csum[e][j * 32 + g] = cs[j];
                        }
                    }
                }
                __syncwarp();
            }
            __syncthreads();
        }

        // ===== Phase C: shared W loads serve both elements =====
        if (tid < 320) {
            const int p  = tid >> 1;
            const int kh = tid & 1;
            const int j  = p >> 4;
            const float4* Wv   = reinterpret_cast<const float4*>(W);
            const float4* cxv0 = reinterpret_cast<const float4*>(S->cx[0]);
            const float4* cxv1 = reinterpret_cast<const float4*>(S->cx[1]);
            float a00 = 0.f, a01 = 0.f, a10 = 0.f, a11 = 0.f;
            #pragma unroll 8
            for (int g = 0; g < 32; g += 2) {
                float4 w0 = Wv[g * 320 + p * 2 + kh];
                float4 w1 = Wv[(g + 1) * 320 + p * 2 + kh];
                a00 += dot4(w0, cxv0[j * 64 + g * 2 + kh]);
                a01 += dot4(w1, cxv0[j * 64 + (g + 1) * 2 + kh]);
                a10 += dot4(w0, cxv1[j * 64 + g * 2 + kh]);
                a11 += dot4(w1, cxv1[j * 64 + (g + 1) * 2 + kh]);
            }
            float acc0 = a00 + a01, acc1 = a10 + a11;
            acc0 += __shfl_xor_sync(0xffffffffu, acc0, 1);
            acc1 += __shfl_xor_sync(0xffffffffu, acc1, 1);
            if (kh == 0) { S->sWsB[0][p] = acc0; S->sWsB[1][p] = acc1; }
        } else if (tid >= 352 && tid < 512) {
            const int p = tid - 352;
            const int j = p >> 4;
            const float4* cs0 = reinterpret_cast<const float4*>(S->csum[0] + j * 32);
            const float4* cs1 = reinterpret_cast<const float4*>(S->csum[1] + j * 32);
            float ab0 = 0.f, ab1 = 0.f;
            #pragma unroll
            for (int gg = 0; gg < 8; gg++) {
                float4 c40 = cs0[gg], c41 = cs1[gg];
                float bv0 = bias[(gg * 4 + 0) * 160 + p];
                float bv1 = bias[(gg * 4 + 1) * 160 + p];
                float bv2 = bias[(gg * 4 + 2) * 160 + p];
                float bv3 = bias[(gg * 4 + 3) * 160 + p];
                ab0 += bv0 * c40.x + bv1 * c40.y + bv2 * c40.z + bv3 * c40.w;
                ab1 += bv0 * c41.x + bv1 * c41.y + bv2 * c41.z + bv3 * c41.w;
            }
            S->sWsB[0][160 + p] = ab0;
            S->sWsB[1][160 + p] = ab1;
        }
        __syncthreads();

        // ===== Phase D: squash + telescoped vsum accumulate =====
        {
            int e = -1, p = 0;
            if (tid < 160) { e = 0; p = tid; }
            else if (tid >= 512 && tid < 672) { e = 1; p = tid - 512; }
            if (e >= 0) {
                float sv = S->sWsB[e][p] + S->sWsB[e][160 + p];
                float n2 = sv * sv;
                n2 += __shfl_xor_sync(0xffffffffu, n2, 1);
                n2 += __shfl_xor_sync(0xffffffffu, n2, 2);
                n2 += __shfl_xor_sync(0xffffffffu, n2, 4);
                n2 += __shfl_xor_sync(0xffffffffu, n2, 8);
                float f  = __fdividef(sqrtf(n2), 1.0f + n2);
                float vv = sv * f;
                if (it == 2) {
                    out[(size_t)(b0 + e) * 160 + p] = vv;
                } else {
                    S->vsum[e][p] = (it == 0) ? LOG2E * vv : S->vsum[e][p] + LOG2E * vv;
                }
            }
        }
        if (it < 2) __syncthreads();
    }
}

extern "C" void kernel_launch(void* const* d_in, const int* in_sizes, int n_in,
                              void* d_out, int out_size) {
    const float* x    = (const float*)d_in[0];
    const float* W    = (const float*)d_in[2];
    const float* bias = (const float*)d_in[3];
    float* out = (float*)d_out;

    transpose_W_kernel<<<160, 256>>>(W);

    cudaFuncSetAttribute(caps_kernel,
                         cudaFuncAttributeMaxDynamicSharedMemorySize,
                         (int)sizeof(Smem));
    caps_kernel<<<256, 1024, sizeof(Smem)>>>(x, W, bias, out);
}

// round 10
// speedup vs baseline: 1.4966x; 1.0767x over previous
#include <cuda_runtime.h>

// CapLayer fused capsule routing. 256 CTAs x 512 threads, 2 CTAs/SM,
// 2 batch elems/CTA (weight loads shared), x served from L1/L2 (not smem).
// x:    d_in[0]  float [512][256][6][6]   (channel = g*8+k, g<32, k<8)
// W:    d_in[2]  float [5120][8] ; flat = g*1280 + j*128 + d*8 + k
// bias: d_in[3]  float [5120]    ; flat = g*160  + j*16  + d
// out:  float [512][10][16]

#define LOG2E 1.4426950408889634f

__device__ float g_WT[40960];   // [g][j][k][d]

struct Smem {
    float cbuf[16][360];  // per-warp c scratch [w][j][hw]
    float scr[16][192];   // per-warp, per-elem 96: [0..79] vW[j][k], [80..89] vb[j]
    float cx[2][2560];    // [e][j][g][k]
    float csum[2][320];   // [e][j][g]
    float sWsB[2][320];   // sW=[0..159], sB=[160..319]; xsum aliases [0..255]
    float vsum[2][160];   // LOG2E * accumulated v, [e][j][d]
};                        // 15552 floats = 62208 B (2 CTAs/SM: 124.4KB)

__device__ __forceinline__ float ex2_approx(float x) {
    float y; asm("ex2.approx.ftz.f32 %0, %1;" : "=f"(y) : "f"(x)); return y;
}
__device__ __forceinline__ float rcp_approx(float x) {
    float y; asm("rcp.approx.ftz.f32 %0, %1;" : "=f"(y) : "f"(x)); return y;
}
__device__ __forceinline__ float dot4(float4 a, float4 b) {
    return a.x * b.x + a.y * b.y + a.z * b.z + a.w * b.w;
}
__device__ __forceinline__ float sum4(float4 a) {
    return a.x + a.y + a.z + a.w;
}

__global__ void transpose_W_kernel(const float* __restrict__ W) {
    int i = blockIdx.x * 256 + threadIdx.x;
    if (i < 40960) {
        int d = i & 15;
        int k = (i >> 4) & 7;
        int gj = i >> 7;
        int j = gj % 10, g = gj / 10;
        g_WT[i] = W[g * 1280 + j * 128 + d * 8 + k];
    }
}

__global__ __launch_bounds__(512, 2)
void caps_kernel(const float* __restrict__ x_g,
                 const float* __restrict__ W,
                 const float* __restrict__ bias,
                 float* __restrict__ out) {
    extern __shared__ float smem_raw[];
    Smem* S = reinterpret_cast<Smem*>(smem_raw);

    const int b0   = blockIdx.x * 2;
    const int tid  = threadIdx.x;
    const int w    = tid >> 5;
    const int lane = tid & 31;

    const float* x0g = x_g + (size_t)b0 * 9216;   // elem 0
    const float* x1g = x0g + 9216;                // elem 1

    // ---- xsum[e][g][k] = sum_hw x (from global; stored in sWsB alias) ----
    if (tid < 512) {
        const int e = tid >> 8, idx = tid & 255;
        const float4* p = reinterpret_cast<const float4*>((e ? x1g : x0g) + idx * 36);
        float4 a4 = p[0];
        #pragma unroll
        for (int t = 1; t < 9; t++) {
            float4 q = p[t];
            a4.x += q.x; a4.y += q.y; a4.z += q.z; a4.w += q.w;
        }
        S->sWsB[e][idx] = sum4(a4);
    }
    __syncthreads();

    // iter 1 shortcut: c uniform 0.1 -> cx = 0.1*xsum (all j), csum = 3.6
    for (int i = tid; i < 5120; i += 512) {
        const int e = (i >= 2560);
        const int ii = i - e * 2560;
        S->cx[0][i] = 0.1f * S->sWsB[e][ii & 255];
    }
    for (int i = tid; i < 640; i += 512) S->csum[0][i] = 3.6f;
    __syncthreads();

    for (int it = 0; it < 3; ++it) {
        if (it > 0) {
            // ===== Phase A-pre + A + B; warp handles groups w and w+16 =====
            #pragma unroll
            for (int gi = 0; gi < 2; gi++) {
                const int g = w + gi * 16;
                float* scr = S->scr[w];

                // --- A-pre: shared WT/bias loads for both elements ---
                {
                    const float4* WTv = reinterpret_cast<const float4*>(g_WT) + g * 320;
                    const float4* vs0 = reinterpret_cast<const float4*>(S->vsum[0]);
                    const float4* vs1 = reinterpret_cast<const float4*>(S->vsum[1]);
                    const int q  = lane & 3;
                    const int jk = lane >> 2;
                    #pragma unroll
                    for (int r = 0; r < 10; r++) {
                        float4 a = WTv[r * 32 + lane];       // coalesced 512B
                        float p0 = dot4(a, vs0[r * 4 + q]);
                        float p1 = dot4(a, vs1[r * 4 + q]);
                        p0 += __shfl_xor_sync(0xffffffffu, p0, 1);
                        p0 += __shfl_xor_sync(0xffffffffu, p0, 2);
                        p1 += __shfl_xor_sync(0xffffffffu, p1, 1);
                        p1 += __shfl_xor_sync(0xffffffffu, p1, 2);
                        if (q == 0) { scr[r * 8 + jk] = p0; scr[96 + r * 8 + jk] = p1; }
                    }
                    const float4* Bv = reinterpret_cast<const float4*>(bias);
                    float4 fa = Bv[g * 40 + lane];
                    float4 fb = Bv[g * 40 + 32 + (lane & 7)];
                    float pa0 = dot4(fa, vs0[lane]);
                    float pa1 = dot4(fa, vs1[lane]);
                    float pb0 = dot4(fb, vs0[32 + (lane & 7)]);
                    float pb1 = dot4(fb, vs1[32 + (lane & 7)]);
                    pa0 += __shfl_xor_sync(0xffffffffu, pa0, 1);
                    pa0 += __shfl_xor_sync(0xffffffffu, pa0, 2);
                    pa1 += __shfl_xor_sync(0xffffffffu, pa1, 1);
                    pa1 += __shfl_xor_sync(0xffffffffu, pa1, 2);
                    pb0 += __shfl_xor_sync(0xffffffffu, pb0, 1);
                    pb0 += __shfl_xor_sync(0xffffffffu, pb0, 2);
                    pb1 += __shfl_xor_sync(0xffffffffu, pb1, 1);
                    pb1 += __shfl_xor_sync(0xffffffffu, pb1, 2);
                    if ((lane & 3) == 0) {
                        scr[80 + (lane >> 2)] = pa0;
                        scr[96 + 80 + (lane >> 2)] = pa1;
                        if (lane < 8) {
                            scr[88 + (lane >> 2)] = pb0;
                            scr[96 + 88 + (lane >> 2)] = pb1;
                        }
                    }
                }
                __syncwarp();

                // --- Phase A+B per element (x from global/L1) ---
                #pragma unroll
                for (int e = 0; e < 2; e++) {
                    const float* se = scr + e * 96;
                    const float* xge = e ? x1g : x0g;
                    // Phase A: logits -> softmax over j -> c
                    {
                        const float* xr = xge + g * 288;
                        float xv[8], xv2[8];
                        #pragma unroll
                        for (int k = 0; k < 8; k++) {
                            xv[k]  = xr[k * 36 + lane];
                            xv2[k] = xr[k * 36 + 32 + (lane & 3)];
                        }
                        float bb[10], bb2[10];
                        #pragma unroll
                        for (int j = 0; j < 10; j++) {
                            const float4* vwp = reinterpret_cast<const float4*>(se + j * 8);
                            float4 w0 = vwp[0], w1 = vwp[1];
                            float t0 = se[80 + j];
                            float a  = t0, a2 = t0;
                            a  += w0.x*xv[0] + w0.y*xv[1] + w0.z*xv[2] + w0.w*xv[3]
                                + w1.x*xv[4] + w1.y*xv[5] + w1.z*xv[6] + w1.w*xv[7];
                            a2 += w0.x*xv2[0] + w0.y*xv2[1] + w0.z*xv2[2] + w0.w*xv2[3]
                                + w1.x*xv2[4] + w1.y*xv2[5] + w1.z*xv2[6] + w1.w*xv2[7];
                            bb[j] = a; bb2[j] = a2;
                        }
                        float Z = 0.f, Z2 = 0.f;
                        #pragma unroll
                        for (int j = 0; j < 10; j++) {
                            bb[j]  = ex2_approx(bb[j]);   Z  += bb[j];
                            bb2[j] = ex2_approx(bb2[j]);  Z2 += bb2[j];
                        }
                        float r  = rcp_approx(Z);
                        float r2 = rcp_approx(Z2);
                        float* cw = S->cbuf[w];
                        #pragma unroll
                        for (int j = 0; j < 10; j++) {
                            cw[j * 36 + lane] = bb[j] * r;
                            if (lane < 4) cw[j * 36 + 32 + lane] = bb2[j] * r2;
                        }
                    }
                    __syncwarp();
                    // Phase B: cx[e][j][g][k] = sum_hw c*x ; csum[e][j][g]
                    {
                        const int k = lane >> 2, q = lane & 3;
                        const float* xr = xge + (g * 8 + k) * 36;
                        float4 x0 = *reinterpret_cast<const float4*>(xr + 4 * q);
                        float4 x1 = *reinterpret_cast<const float4*>(xr + 16 + 4 * q);
                        float  x2 = xr[32 + q];
                        const float* cb = S->cbuf[w];
                        float acc[10], cs[10];
                        #pragma unroll
                        for (int j = 0; j < 10; j++) {
                            float4 c0 = *reinterpret_cast<const float4*>(cb + j * 36 + 4 * q);
                            float4 c1 = *reinterpret_cast<const float4*>(cb + j * 36 + 16 + 4 * q);
                            float  c2 = cb[j * 36 + 32 + q];
                            acc[j] = dot4(c0, x0) + dot4(c1, x1) + c2 * x2;
                            cs[j]  = sum4(c0) + sum4(c1) + c2;
                        }
                        #pragma unroll
                        for (int j = 0; j < 10; j++) {
                            acc[j] += __shfl_xor_sync(0xffffffffu, acc[j], 1);
                            acc[j] += __shfl_xor_sync(0xffffffffu, acc[j], 2);
                            cs[j]  += __shfl_xor_sync(0xffffffffu, cs[j], 1);
                            cs[j]  += __shfl_xor_sync(0xffffffffu, cs[j], 2);
                        }
                        if (q == 0) {
                            #pragma unroll
                            for (int j = 0; j < 10; j++) S->cx[e][j * 256 + g * 8 + k] = acc[j];
                            if (k == 0) {
                                #pragma unroll
                                for (int j = 0; j < 10; j++) S->csum[e][j * 32 + g] = cs[j];
                            }
                        }
                    }
                    __syncwarp();
                }
            }
            __syncthreads();
        }

        // ===== Phase C: shared W/bias loads serve both elements =====
        if (tid < 320) {
            const int p  = tid >> 1;
            const int kh = tid & 1;
            const int j  = p >> 4;
            const float4* Wv   = reinterpret_cast<const float4*>(W);
            const float4* cxv0 = reinterpret_cast<const float4*>(S->cx[0]);
            const float4* cxv1 = reinterpret_cast<const float4*>(S->cx[1]);
            float a00 = 0.f, a01 = 0.f, a10 = 0.f, a11 = 0.f;
            #pragma unroll 8
            for (int g = 0; g < 32; g += 2) {
                float4 w0 = Wv[g * 320 + p * 2 + kh];
                float4 w1 = Wv[(g + 1) * 320 + p * 2 + kh];
                a00 += dot4(w0, cxv0[j * 64 + g * 2 + kh]);
                a01 += dot4(w1, cxv0[j * 64 + (g + 1) * 2 + kh]);
                a10 += dot4(w0, cxv1[j * 64 + g * 2 + kh]);
                a11 += dot4(w1, cxv1[j * 64 + (g + 1) * 2 + kh]);
            }
            float acc0 = a00 + a01, acc1 = a10 + a11;
            acc0 += __shfl_xor_sync(0xffffffffu, acc0, 1);
            acc1 += __shfl_xor_sync(0xffffffffu, acc1, 1);
            if (kh == 0) { S->sWsB[0][p] = acc0; S->sWsB[1][p] = acc1; }
        } else if (tid >= 352) {
            const int p = tid - 352;     // 0..159
            const int j = p >> 4;
            const float4* cs0 = reinterpret_cast<const float4*>(S->csum[0] + j * 32);
            const float4* cs1 = reinterpret_cast<const float4*>(S->csum[1] + j * 32);
            float ab0 = 0.f, ab1 = 0.f;
            #pragma unroll
            for (int gg = 0; gg < 8; gg++) {
                float4 c40 = cs0[gg], c41 = cs1[gg];
                float bv0 = bias[(gg * 4 + 0) * 160 + p];
                float bv1 = bias[(gg * 4 + 1) * 160 + p];
                float bv2 = bias[(gg * 4 + 2) * 160 + p];
                float bv3 = bias[(gg * 4 + 3) * 160 + p];
                ab0 += bv0 * c40.x + bv1 * c40.y + bv2 * c40.z + bv3 * c40.w;
                ab1 += bv0 * c41.x + bv1 * c41.y + bv2 * c41.z + bv3 * c41.w;
            }
            S->sWsB[0][160 + p] = ab0;
            S->sWsB[1][160 + p] = ab1;
        }
        __syncthreads();

        // ===== Phase D: squash + telescoped vsum accumulate =====
        {
            int e = -1, p = 0;
            if (tid < 160) { e = 0; p = tid; }
            else if (tid >= 256 && tid < 416) { e = 1; p = tid - 256; }
            if (e >= 0) {
                float sv = S->sWsB[e][p] + S->sWsB[e][160 + p];
                float n2 = sv * sv;
                n2 += __shfl_xor_sync(0xffffffffu, n2, 1);
                n2 += __shfl_xor_sync(0xffffffffu, n2, 2);
                n2 += __shfl_xor_sync(0xffffffffu, n2, 4);
                n2 += __shfl_xor_sync(0xffffffffu, n2, 8);
                float f  = __fdividef(sqrtf(n2), 1.0f + n2);
                float vv = sv * f;
                if (it == 2) {
                    out[(size_t)(b0 + e) * 160 + p] = vv;
                } else {
                    S->vsum[e][p] = (it == 0) ? LOG2E * vv : S->vsum[e][p] + LOG2E * vv;
                }
            }
        }
        if (it < 2) __syncthreads();
    }
}

extern "C" void kernel_launch(void* const* d_in, const int* in_sizes, int n_in,
                              void* d_out, int out_size) {
    const float* x    = (const float*)d_in[0];
    const float* W    = (const float*)d_in[2];
    const float* bias = (const float*)d_in[3];
    float* out = (float*)d_out;

    transpose_W_kernel<<<160, 256>>>(W);

    cudaFuncSetAttribute(caps_kernel,
                         cudaFuncAttributeMaxDynamicSharedMemorySize,
                         (int)sizeof(Smem));
    caps_kernel<<<256, 512, sizeof(Smem)>>>(x, W, bias, out);
}